// round 1
// baseline (speedup 1.0000x reference)
#include <cuda_runtime.h>
#include <cstdint>

// Gated delta rule recurrence: S_t = S_{t-1} @ A_t + B_t
// A,Bm: [T, B, H, D, D] fp32;  init_state: [B, H, D, D];  out: [T, B, H, D, D]
// T=128, B*H=64 chains, D=64.
//
// Strategy: rows of S are independent -> split each chain's 64 rows into 2 CTAs
// of 32 rows. 128 CTAs, 128 threads each (thread tile = 2 rows x 8 cols).
// Full fp32 math via packed fma.rn.f32x2 (2x FFMA issue rate vs 3-reg FFMA).
// S lives in smem transposed [k][r] (double buffered); A_t double buffered via
// cp.async prefetch; Bm prefetched into registers one step ahead.

#define T_DIM 128
#define BH 64
#define D 64
#define ROWS 32
#define THREADS 128
#define TSTRIDE (BH * D * D)   // 262144 floats per time slice

__device__ __forceinline__ uint32_t smem_u32(const void* p) {
    return (uint32_t)__cvta_generic_to_shared(p);
}
__device__ __forceinline__ unsigned long long pk2(float lo, float hi) {
    unsigned long long r;
    asm("mov.b64 %0,{%1,%2};" : "=l"(r) : "f"(lo), "f"(hi));
    return r;
}
__device__ __forceinline__ void upk2(unsigned long long v, float& lo, float& hi) {
    asm("mov.b64 {%0,%1},%2;" : "=f"(lo), "=f"(hi) : "l"(v));
}
__device__ __forceinline__ unsigned long long f2fma(unsigned long long a,
                                                    unsigned long long b,
                                                    unsigned long long c) {
    unsigned long long d;
    asm("fma.rn.f32x2 %0,%1,%2,%3;" : "=l"(d) : "l"(a), "l"(b), "l"(c));
    return d;
}

__global__ void __launch_bounds__(THREADS, 1) gdr_kernel(
    const float* __restrict__ A,
    const float* __restrict__ Bm,
    const float* __restrict__ S0,
    float* __restrict__ out)
{
    __shared__ float Abuf[2][D * D];      // 2 x 16 KB
    __shared__ float Sbuf[2][D * ROWS];   // 2 x 8 KB, transposed: [k][r_local]

    const int tid   = threadIdx.x;
    const int chain = blockIdx.x >> 1;    // 0..63  (b*H + h)
    const int half  = blockIdx.x & 1;     // which 32-row half
    const int r0base = half * ROWS;

    const int rg  = tid & 15;             // row group (2 rows each)
    const int cg  = tid >> 4;             // col group (8 cols each)
    const int j0  = cg * 8;
    const int rl0 = rg * 2;               // local row (even)

    const long chainOff = (long)chain * (D * D);

    // ---------------- prologue ----------------
    // Prefetch A[0] into Abuf[0] via cp.async (16 KB, coalesced).
    {
        uint32_t s = smem_u32(&Abuf[0][0]) + tid * 16;
        const float* g = A + chainOff + tid * 4;
        #pragma unroll
        for (int i = 0; i < 8; i++) {
            asm volatile("cp.async.cg.shared.global [%0],[%1],16;"
                         :: "r"(s + i * 2048), "l"(g + i * 512));
        }
        asm volatile("cp.async.commit_group;");
    }

    // Bm[0] -> registers (2 rows x 8 cols)
    float4 bm00, bm01, bm10, bm11;
    {
        const float* g = Bm + chainOff + (long)(r0base + rl0) * D + j0;
        bm00 = *(const float4*)(g);
        bm01 = *(const float4*)(g + 4);
        bm10 = *(const float4*)(g + D);
        bm11 = *(const float4*)(g + D + 4);
    }

    // Init Sbuf[0] from init_state, transposed: Sbuf[0][k*ROWS + r] = S0[r][k]
    {
        int rl = tid & 31;
        int kb = (tid >> 5) * 16;
        const float* g = S0 + chainOff + (long)(r0base + rl) * D + kb;
        #pragma unroll
        for (int kk = 0; kk < 16; kk++)
            Sbuf[0][(kb + kk) * ROWS + rl] = g[kk];
    }

    // ---------------- main time loop ----------------
    for (int t = 0; t < T_DIM; t++) {
        // A[t] cp.async group done (issued last iter / prologue)
        asm volatile("cp.async.wait_group 0;" ::: "memory");
        // also publishes Sbuf writes of the previous step
        __syncthreads();

        const int cur = t & 1;

        // Prefetch A[t+1] into the other buffer (safe: freed by the barrier).
        if (t + 1 < T_DIM) {
            uint32_t s = smem_u32(&Abuf[cur ^ 1][0]) + tid * 16;
            const float* g = A + (long)(t + 1) * TSTRIDE + chainOff + tid * 4;
            #pragma unroll
            for (int i = 0; i < 8; i++) {
                asm volatile("cp.async.cg.shared.global [%0],[%1],16;"
                             :: "r"(s + i * 2048), "l"(g + i * 512));
            }
            asm volatile("cp.async.commit_group;");
        }

        // acc := Bm[t]  (from registers loaded one step ahead)
        unsigned long long a0[4], a1[4];
        a0[0] = pk2(bm00.x, bm00.y); a0[1] = pk2(bm00.z, bm00.w);
        a0[2] = pk2(bm01.x, bm01.y); a0[3] = pk2(bm01.z, bm01.w);
        a1[0] = pk2(bm10.x, bm10.y); a1[1] = pk2(bm10.z, bm10.w);
        a1[2] = pk2(bm11.x, bm11.y); a1[3] = pk2(bm11.z, bm11.w);

        // Prefetch Bm[t+1] into registers (overlaps with the k-loop).
        if (t + 1 < T_DIM) {
            const float* g = Bm + (long)(t + 1) * TSTRIDE + chainOff
                           + (long)(r0base + rl0) * D + j0;
            bm00 = *(const float4*)(g);
            bm01 = *(const float4*)(g + 4);
            bm10 = *(const float4*)(g + D);
            bm11 = *(const float4*)(g + D + 4);
        }

        // k-loop: acc[r][j] += S[r][k] * A[k][j]
        uint32_t aAddr = smem_u32(&Abuf[cur][0]) + j0 * 4;
        uint32_t sAddr = smem_u32(&Sbuf[cur][0]) + rl0 * 4;
        #pragma unroll
        for (int k = 0; k < D; k++) {
            unsigned long long av0, av1, av2, av3, sp;
            asm("ld.shared.v2.b64 {%0,%1},[%2];"
                : "=l"(av0), "=l"(av1) : "r"(aAddr));
            asm("ld.shared.v2.b64 {%0,%1},[%2];"
                : "=l"(av2), "=l"(av3) : "r"(aAddr + 16));
            asm("ld.shared.b64 %0,[%1];" : "=l"(sp) : "r"(sAddr));
            float s0f, s1f;
            upk2(sp, s0f, s1f);
            unsigned long long s0 = pk2(s0f, s0f);
            unsigned long long s1 = pk2(s1f, s1f);
            a0[0] = f2fma(s0, av0, a0[0]);
            a0[1] = f2fma(s0, av1, a0[1]);
            a0[2] = f2fma(s0, av2, a0[2]);
            a0[3] = f2fma(s0, av3, a0[3]);
            a1[0] = f2fma(s1, av0, a1[0]);
            a1[1] = f2fma(s1, av1, a1[1]);
            a1[2] = f2fma(s1, av2, a1[2]);
            a1[3] = f2fma(s1, av3, a1[3]);
            aAddr += D * 4;
            sAddr += ROWS * 4;
        }

        // Epilogue: unpack, store to gmem, write Snew transposed to next Sbuf.
        float r0f[8], r1f[8];
        upk2(a0[0], r0f[0], r0f[1]); upk2(a0[1], r0f[2], r0f[3]);
        upk2(a0[2], r0f[4], r0f[5]); upk2(a0[3], r0f[6], r0f[7]);
        upk2(a1[0], r1f[0], r1f[1]); upk2(a1[1], r1f[2], r1f[3]);
        upk2(a1[2], r1f[4], r1f[5]); upk2(a1[3], r1f[6], r1f[7]);

        float* o = out + (long)t * TSTRIDE + chainOff
                 + (long)(r0base + rl0) * D + j0;
        *(float4*)(o)         = make_float4(r0f[0], r0f[1], r0f[2], r0f[3]);
        *(float4*)(o + 4)     = make_float4(r0f[4], r0f[5], r0f[6], r0f[7]);
        *(float4*)(o + D)     = make_float4(r1f[0], r1f[1], r1f[2], r1f[3]);
        *(float4*)(o + D + 4) = make_float4(r1f[4], r1f[5], r1f[6], r1f[7]);

        float* sb = &Sbuf[cur ^ 1][0];
        #pragma unroll
        for (int jj = 0; jj < 8; jj++) {
            *(unsigned long long*)&sb[(j0 + jj) * ROWS + rl0] =
                pk2(r0f[jj], r1f[jj]);
        }
        // next iteration's __syncthreads publishes Sbuf[cur^1]
    }
}

extern "C" void kernel_launch(void* const* d_in, const int* in_sizes, int n_in,
                              void* d_out, int out_size) {
    const float* A  = (const float*)d_in[0];
    const float* Bm = (const float*)d_in[1];
    const float* S0 = (const float*)d_in[2];
    float* out = (float*)d_out;
    (void)in_sizes; (void)n_in; (void)out_size;

    gdr_kernel<<<BH * 2, THREADS>>>(A, Bm, S0, out);
}